// round 6
// baseline (speedup 1.0000x reference)
#include <cuda_runtime.h>
#include <cuda_fp16.h>
#include <cstdint>
#include <math.h>

// ---------------- problem constants ----------------
#define B_SZ 16
#define H_SZ 8
#define L_SZ 1024
#define E_SZ 64
#define RS   512                 // floats between consecutive rows (H*E)

#define BM 128
#define BN 64
#define NT 16
#define THREADS 256

// ---------------- smem byte map (fp16 tiles, 128B swizzled rows) ------------
#define QO   0                       // 128 x 64 fp16 = 16 KB
#define KO(b) (16384 + (b) * 8192)   // 64 x 64 fp16, double buffered
#define VO(b) (32768 + (b) * 8192)
#define LSO  49152                   // 128 x 2 fp32 partial row sums
#define SMEM_BYTES 50176
#define OBS  66                      // epilogue O-buffer row stride (floats)

// g_w[l][s] = softmax_s(wm[l][s]/softplus(tau[l])) * (1/8) * log2(e)
__device__ float g_w[L_SZ * L_SZ];

// ---------------- helpers ----------------
__device__ __forceinline__ uint32_t smem_u32(const void* p) {
    uint32_t a;
    asm("{ .reg .u64 t; cvta.to.shared.u64 t, %1; cvt.u32.u64 %0, t; }" : "=r"(a) : "l"(p));
    return a;
}
// 128B-row XOR swizzle
__device__ __forceinline__ uint32_t swz(int r, int cb) {
    return (uint32_t)(r * 128 + (cb ^ ((r & 7) << 4)));
}
__device__ __forceinline__ float ex2f(float x) {
    float y; asm("ex2.approx.f32 %0, %1;" : "=f"(y) : "f"(x)); return y;
}

#define LDSM4(d0,d1,d2,d3,a) \
    asm volatile("ldmatrix.sync.aligned.m8n8.x4.shared.b16 {%0,%1,%2,%3}, [%4];" \
        : "=r"(d0),"=r"(d1),"=r"(d2),"=r"(d3) : "r"(a))
#define LDSM4T(d0,d1,d2,d3,a) \
    asm volatile("ldmatrix.sync.aligned.m8n8.x4.trans.shared.b16 {%0,%1,%2,%3}, [%4];" \
        : "=r"(d0),"=r"(d1),"=r"(d2),"=r"(d3) : "r"(a))
#define MMA16816(c, a0,a1,a2,a3, b0,b1) \
    asm volatile("mma.sync.aligned.m16n8k16.row.col.f32.f16.f16.f32 " \
        "{%0,%1,%2,%3},{%4,%5,%6,%7},{%8,%9},{%0,%1,%2,%3};" \
        : "+f"((c)[0]),"+f"((c)[1]),"+f"((c)[2]),"+f"((c)[3]) \
        : "r"(a0),"r"(a1),"r"(a2),"r"(a3),"r"(b0),"r"(b1))

__device__ __forceinline__ uint2 pack4h(float4 x) {
    half2 h0 = __floats2half2_rn(x.x, x.y);
    half2 h1 = __floats2half2_rn(x.z, x.w);
    return make_uint2(*(uint32_t*)&h0, *(uint32_t*)&h1);
}

// ---------------- kernel 1: modulation weights ----------------
__global__ void wprep_kernel(const float* __restrict__ wm, const float* __restrict__ tau) {
    __shared__ float red_m[8];
    __shared__ float red_s[8];
    const int row = blockIdx.x, tid = threadIdx.x;
    const int warp = tid >> 5, lane = tid & 31;

    float t = tau[row];
    float sp = (t > 20.f) ? t : log1pf(__expf(t));
    float inv = 1.f / sp;

    float4 x = reinterpret_cast<const float4*>(wm + (size_t)row * L_SZ)[tid];
    x.x *= inv; x.y *= inv; x.z *= inv; x.w *= inv;

    float mx = fmaxf(fmaxf(x.x, x.y), fmaxf(x.z, x.w));
    #pragma unroll
    for (int o = 16; o; o >>= 1) mx = fmaxf(mx, __shfl_xor_sync(0xffffffffu, mx, o));
    if (lane == 0) red_m[warp] = mx;
    __syncthreads();
    float M = red_m[0];
    #pragma unroll
    for (int i = 1; i < 8; i++) M = fmaxf(M, red_m[i]);

    float e0 = __expf(x.x - M), e1 = __expf(x.y - M);
    float e2 = __expf(x.z - M), e3 = __expf(x.w - M);
    float s = e0 + e1 + e2 + e3;
    #pragma unroll
    for (int o = 16; o; o >>= 1) s += __shfl_xor_sync(0xffffffffu, s, o);
    if (lane == 0) red_s[warp] = s;
    __syncthreads();
    float S = 0.f;
    #pragma unroll
    for (int i = 0; i < 8; i++) S += red_s[i];

    float f = 0.125f / S * 1.44269504089f;   // fold 1/sqrt(E) and log2(e)
    reinterpret_cast<float4*>(g_w + (size_t)row * L_SZ)[tid] =
        make_float4(e0 * f, e1 * f, e2 * f, e3 * f);
}

// ---------------- kernel 2: fp16 mma flash attention, 2 CTAs/SM ------------
__global__ void __launch_bounds__(THREADS, 2)
flash_kernel(const float* __restrict__ q, const float* __restrict__ kmat,
             const float* __restrict__ v, float* __restrict__ out) {
    extern __shared__ char smem[];
    const uint32_t sb = smem_u32(smem);

    const int tid = threadIdx.x;
    const int warp = tid >> 5, lane = tid & 31;
    const int mw = warp >> 1, nw = warp & 1;     // 4 M-warps x 2 K-split warps
    const int g = lane >> 2, t4 = lane & 3;
    const int l0 = blockIdx.x * BM;

    const size_t base = (size_t)(blockIdx.y >> 3) * (L_SZ * RS) + (size_t)(blockIdx.y & 7) * E_SZ;
    const float* qb = q + base;
    const float* kb = kmat + base;
    const float* vb = v + base;
    float* ob = out + base;

    // ---- prologue: stage Q / K0 / V0 as swizzled fp16 ----
    #pragma unroll
    for (int i = 0; i < 8; i++) {
        int e4 = i * THREADS + tid;
        int r = e4 >> 4, c = (e4 & 15) << 2;
        float4 x = *(const float4*)(qb + (size_t)(l0 + r) * RS + c);
        *(uint2*)(smem + QO + swz(r, c * 2)) = pack4h(x);
    }
    #pragma unroll
    for (int i = 0; i < 4; i++) {
        int e4 = i * THREADS + tid;
        int r = e4 >> 4, c = (e4 & 15) << 2;
        float4 xk = *(const float4*)(kb + (size_t)r * RS + c);
        *(uint2*)(smem + KO(0) + swz(r, c * 2)) = pack4h(xk);
        float4 xv = *(const float4*)(vb + (size_t)r * RS + c);
        *(uint2*)(smem + VO(0) + swz(r, c * 2)) = pack4h(xv);
    }

    float O[2][8][4];
    #pragma unroll
    for (int mb = 0; mb < 2; mb++)
        #pragma unroll
        for (int nb = 0; nb < 8; nb++) {
            O[mb][nb][0] = 0.f; O[mb][nb][1] = 0.f; O[mb][nb][2] = 0.f; O[mb][nb][3] = 0.f;
        }
    float ls[4] = {0.f, 0.f, 0.f, 0.f};

    const int ldr = tid >> 4;                // 0..15
    const int ldc = (tid & 15) << 2;         // 0..60 step 4

    for (int st = 0; st < NT; st++) {
        __syncthreads();     // tiles in buf visible; buf^1 free for overwrite
        const int buf = st & 1;

        // prefetch next K into regs
        float4 kq[4];
        if (st < NT - 1) {
            const int s0n = (st + 1) * BN;
            #pragma unroll
            for (int i = 0; i < 4; i++)
                kq[i] = *(const float4*)(kb + (size_t)(s0n + i * 16 + ldr) * RS + ldc);
        }

        uint32_t P[2][2][4];     // fp16 A-frags for PV (this warp's 32x32 P block)

        // ---- S + softmax, per 16-col group (kb2) ----
        #pragma unroll
        for (int kb2 = 0; kb2 < 2; kb2++) {
            float S[2][2][4];
            #pragma unroll
            for (int mb = 0; mb < 2; mb++)
                #pragma unroll
                for (int ns = 0; ns < 2; ns++) {
                    S[mb][ns][0] = 0.f; S[mb][ns][1] = 0.f; S[mb][ns][2] = 0.f; S[mb][ns][3] = 0.f;
                }
            #pragma unroll
            for (int kbk = 0; kbk < 4; kbk++) {
                uint32_t Kf0, Kf1, Kf2, Kf3;
                {
                    int rk = 32 * nw + 16 * kb2 + (lane & 7) + ((lane & 16) >> 1);
                    int cbk = kbk * 32 + (((lane >> 3) & 1) << 4);
                    LDSM4(Kf0, Kf1, Kf2, Kf3, sb + KO(buf) + swz(rk, cbk));
                }
                #pragma unroll
                for (int mb = 0; mb < 2; mb++) {
                    uint32_t Qf0, Qf1, Qf2, Qf3;
                    LDSM4(Qf0, Qf1, Qf2, Qf3,
                          sb + QO + swz(32 * mw + 16 * mb + (lane & 15),
                                        kbk * 32 + ((lane >> 4) << 4)));
                    MMA16816(S[mb][0], Qf0, Qf1, Qf2, Qf3, Kf0, Kf1);
                    MMA16816(S[mb][1], Qf0, Qf1, Qf2, Qf3, Kf2, Kf3);
                }
            }
            // softmax: p = exp2(s * w'), w' has log2e folded; |z|<<1 -> no max
            #pragma unroll
            for (int mb = 0; mb < 2; mb++) {
                const float* wr = g_w + (size_t)(l0 + 32 * mw + 16 * mb + g) * L_SZ
                                  + st * BN + 32 * nw + 16 * kb2 + 2 * t4;
                #pragma unroll
                for (int ns = 0; ns < 2; ns++) {
                    float2 wa = *(const float2*)(wr + ns * 8);
                    float2 wb = *(const float2*)(wr + ns * 8 + 8 * L_SZ);
                    float e0 = ex2f(S[mb][ns][0] * wa.x);
                    float e1 = ex2f(S[mb][ns][1] * wa.y);
                    float e2 = ex2f(S[mb][ns][2] * wb.x);
                    float e3 = ex2f(S[mb][ns][3] * wb.y);
                    ls[mb * 2 + 0] += e0 + e1;
                    ls[mb * 2 + 1] += e2 + e3;
                    half2 h0 = __floats2half2_rn(e0, e1);
                    half2 h1 = __floats2half2_rn(e2, e3);
                    P[mb][kb2][ns * 2]     = *(uint32_t*)&h0;   // a0 / a2
                    P[mb][kb2][ns * 2 + 1] = *(uint32_t*)&h1;   // a1 / a3
                }
            }
        }

        // store next K; prefetch next V
        float4 vq[4];
        if (st < NT - 1) {
            #pragma unroll
            for (int i = 0; i < 4; i++)
                *(uint2*)(smem + KO(buf ^ 1) + swz(i * 16 + ldr, ldc * 2)) = pack4h(kq[i]);
            const int s0n = (st + 1) * BN;
            #pragma unroll
            for (int i = 0; i < 4; i++)
                vq[i] = *(const float4*)(vb + (size_t)(s0n + i * 16 + ldr) * RS + ldc);
        }

        // ---- O_partial += P * V (k-rows 32*nw..+31) ----
        #pragma unroll
        for (int kb2 = 0; kb2 < 2; kb2++) {
            uint32_t Vf[4][4];
            #pragma unroll
            for (int n16 = 0; n16 < 4; n16++) {
                int rv = 32 * nw + 16 * kb2 + (lane & 15);
                int cbv = n16 * 32 + ((lane >> 4) << 4);
                LDSM4T(Vf[n16][0], Vf[n16][1], Vf[n16][2], Vf[n16][3],
                       sb + VO(buf) + swz(rv, cbv));
            }
            #pragma unroll
            for (int mb = 0; mb < 2; mb++)
                #pragma unroll
                for (int nb = 0; nb < 8; nb++)
                    MMA16816(O[mb][nb], P[mb][kb2][0], P[mb][kb2][1], P[mb][kb2][2], P[mb][kb2][3],
                             Vf[nb >> 1][(nb & 1) * 2], Vf[nb >> 1][(nb & 1) * 2 + 1]);
        }

        // store next V
        if (st < NT - 1) {
            #pragma unroll
            for (int i = 0; i < 4; i++)
                *(uint2*)(smem + VO(buf ^ 1) + swz(i * 16 + ldr, ldc * 2)) = pack4h(vq[i]);
        }
    }

    // ---- epilogue: combine k-halves (nw 0/1) and row sums, store ----
    __syncthreads();    // all PV reads done; smem reusable

    #pragma unroll
    for (int j = 0; j < 4; j++) {
        ls[j] += __shfl_xor_sync(0xffffffffu, ls[j], 1);
        ls[j] += __shfl_xor_sync(0xffffffffu, ls[j], 2);
    }
    float* LS = (float*)(smem + LSO);
    if (t4 == 0) {
        #pragma unroll
        for (int mb = 0; mb < 2; mb++)
            #pragma unroll
            for (int hf = 0; hf < 2; hf++)
                LS[(32 * mw + 16 * mb + 8 * hf + g) * 2 + nw] = ls[mb * 2 + hf];
    }
    float* OB = (float*)smem;    // 128 x OBS scratch (overlaps dead Q/K tiles)
    if (nw == 0) {
        #pragma unroll
        for (int mb = 0; mb < 2; mb++) {
            int r = 32 * mw + 16 * mb + g;
            #pragma unroll
            for (int nb = 0; nb < 8; nb++) {
                int c = 8 * nb + 2 * t4;
                *(float2*)(OB + r * OBS + c) = make_float2(O[mb][nb][0], O[mb][nb][1]);
                *(float2*)(OB + (r + 8) * OBS + c) = make_float2(O[mb][nb][2], O[mb][nb][3]);
            }
        }
    }
    __syncthreads();
    if (nw == 1) {
        #pragma unroll
        for (int mb = 0; mb < 2; mb++) {
            int r = 32 * mw + 16 * mb + g;
            float inv0 = 1.f / (LS[r * 2] + LS[r * 2 + 1]);
            float inv1 = 1.f / (LS[(r + 8) * 2] + LS[(r + 8) * 2 + 1]);
            #pragma unroll
            for (int nb = 0; nb < 8; nb++) {
                int c = 8 * nb + 2 * t4;
                float2 p0 = *(float2*)(OB + r * OBS + c);
                float2 p1 = *(float2*)(OB + (r + 8) * OBS + c);
                *(float2*)(ob + (size_t)(l0 + r) * RS + c) =
                    make_float2((O[mb][nb][0] + p0.x) * inv0, (O[mb][nb][1] + p0.y) * inv0);
                *(float2*)(ob + (size_t)(l0 + r + 8) * RS + c) =
                    make_float2((O[mb][nb][2] + p1.x) * inv1, (O[mb][nb][3] + p1.y) * inv1);
            }
        }
    }
}

// ---------------- launcher ----------------
extern "C" void kernel_launch(void* const* d_in, const int* in_sizes, int n_in,
                              void* d_out, int out_size) {
    const float* q   = (const float*)d_in[0];
    const float* k   = (const float*)d_in[1];
    const float* v   = (const float*)d_in[2];
    const float* wm  = (const float*)d_in[3];
    const float* tau = (const float*)d_in[4];
    // d_in[5] = attn_mask, unused (mask_flag=False)

    cudaFuncSetAttribute(flash_kernel, cudaFuncAttributeMaxDynamicSharedMemorySize, SMEM_BYTES);

    wprep_kernel<<<L_SZ, 256>>>(wm, tau);

    dim3 grid(L_SZ / BM, B_SZ * H_SZ);
    flash_kernel<<<grid, THREADS, SMEM_BYTES>>>(q, k, v, (float*)d_out);
}

// round 7
// speedup vs baseline: 1.0014x; 1.0014x over previous
#include <cuda_runtime.h>
#include <cuda_fp16.h>
#include <cstdint>
#include <math.h>

// ---------------- problem constants ----------------
#define B_SZ 16
#define H_SZ 8
#define L_SZ 1024
#define E_SZ 64
#define RS   512                 // floats between consecutive rows (H*E)

#define BM 128
#define BN 64
#define NT 16
#define THREADS 256

// ---------------- smem byte map (fp16 tiles, 128B swizzled rows) ------------
#define QO   0                       // 128 x 64 fp16 = 16 KB
#define KO(b) (16384 + (b) * 8192)   // 64 x 64 fp16, double buffered
#define VO(b) (32768 + (b) * 8192)
#define LSO  49152                   // 128 x 2 fp32 partial row sums
#define SMEM_BYTES 50176
#define OBS  66                      // epilogue O-buffer row stride (floats)

// g_w[l][s] = softmax_s(wm[l][s]/softplus(tau[l])) * (1/8) * log2(e)
__device__ float g_w[L_SZ * L_SZ];

// ---------------- helpers ----------------
__device__ __forceinline__ uint32_t smem_u32(const void* p) {
    uint32_t a;
    asm("{ .reg .u64 t; cvta.to.shared.u64 t, %1; cvt.u32.u64 %0, t; }" : "=r"(a) : "l"(p));
    return a;
}
// 128B-row XOR swizzle
__device__ __forceinline__ uint32_t swz(int r, int cb) {
    return (uint32_t)(r * 128 + (cb ^ ((r & 7) << 4)));
}
__device__ __forceinline__ float ex2f(float x) {
    float y; asm("ex2.approx.f32 %0, %1;" : "=f"(y) : "f"(x)); return y;
}

#define LDSM4(d0,d1,d2,d3,a) \
    asm volatile("ldmatrix.sync.aligned.m8n8.x4.shared.b16 {%0,%1,%2,%3}, [%4];" \
        : "=r"(d0),"=r"(d1),"=r"(d2),"=r"(d3) : "r"(a))
#define LDSM4T(d0,d1,d2,d3,a) \
    asm volatile("ldmatrix.sync.aligned.m8n8.x4.trans.shared.b16 {%0,%1,%2,%3}, [%4];" \
        : "=r"(d0),"=r"(d1),"=r"(d2),"=r"(d3) : "r"(a))
#define MMA16816(c, a0,a1,a2,a3, b0,b1) \
    asm volatile("mma.sync.aligned.m16n8k16.row.col.f32.f16.f16.f32 " \
        "{%0,%1,%2,%3},{%4,%5,%6,%7},{%8,%9},{%0,%1,%2,%3};" \
        : "+f"((c)[0]),"+f"((c)[1]),"+f"((c)[2]),"+f"((c)[3]) \
        : "r"(a0),"r"(a1),"r"(a2),"r"(a3),"r"(b0),"r"(b1))

__device__ __forceinline__ uint2 pack4h(float4 x) {
    half2 h0 = __floats2half2_rn(x.x, x.y);
    half2 h1 = __floats2half2_rn(x.z, x.w);
    return make_uint2(*(uint32_t*)&h0, *(uint32_t*)&h1);
}

// ---------------- kernel 1: modulation weights ----------------
__global__ void wprep_kernel(const float* __restrict__ wm, const float* __restrict__ tau) {
    __shared__ float red_m[8];
    __shared__ float red_s[8];
    const int row = blockIdx.x, tid = threadIdx.x;
    const int warp = tid >> 5, lane = tid & 31;

    float t = tau[row];
    float sp = (t > 20.f) ? t : log1pf(__expf(t));
    float inv = 1.f / sp;

    float4 x = reinterpret_cast<const float4*>(wm + (size_t)row * L_SZ)[tid];
    x.x *= inv; x.y *= inv; x.z *= inv; x.w *= inv;

    float mx = fmaxf(fmaxf(x.x, x.y), fmaxf(x.z, x.w));
    #pragma unroll
    for (int o = 16; o; o >>= 1) mx = fmaxf(mx, __shfl_xor_sync(0xffffffffu, mx, o));
    if (lane == 0) red_m[warp] = mx;
    __syncthreads();
    float M = red_m[0];
    #pragma unroll
    for (int i = 1; i < 8; i++) M = fmaxf(M, red_m[i]);

    float e0 = __expf(x.x - M), e1 = __expf(x.y - M);
    float e2 = __expf(x.z - M), e3 = __expf(x.w - M);
    float s = e0 + e1 + e2 + e3;
    #pragma unroll
    for (int o = 16; o; o >>= 1) s += __shfl_xor_sync(0xffffffffu, s, o);
    if (lane == 0) red_s[warp] = s;
    __syncthreads();
    float S = 0.f;
    #pragma unroll
    for (int i = 0; i < 8; i++) S += red_s[i];

    float f = 0.125f / S * 1.44269504089f;   // fold 1/sqrt(E) and log2(e)
    reinterpret_cast<float4*>(g_w + (size_t)row * L_SZ)[tid] =
        make_float4(e0 * f, e1 * f, e2 * f, e3 * f);
}

// ---------------- kernel 2: fp16 mma flash attention, 2 CTAs/SM ------------
__global__ void __launch_bounds__(THREADS, 2)
flash_kernel(const float* __restrict__ q, const float* __restrict__ kmat,
             const float* __restrict__ v, float* __restrict__ out) {
    extern __shared__ char smem[];
    const uint32_t sb = smem_u32(smem);

    const int tid = threadIdx.x;
    const int warp = tid >> 5, lane = tid & 31;
    const int mw = warp >> 1, nw = warp & 1;     // 4 M-warps x 2 K-split warps
    const int g = lane >> 2, t4 = lane & 3;
    const int l0 = blockIdx.x * BM;

    const size_t base = (size_t)(blockIdx.y >> 3) * (L_SZ * RS) + (size_t)(blockIdx.y & 7) * E_SZ;
    const float* qb = q + base;
    const float* kb = kmat + base;
    const float* vb = v + base;
    float* ob = out + base;

    // ---- prologue: stage Q / K0 / V0 as swizzled fp16 ----
    #pragma unroll
    for (int i = 0; i < 8; i++) {
        int e4 = i * THREADS + tid;
        int r = e4 >> 4, c = (e4 & 15) << 2;
        float4 x = *(const float4*)(qb + (size_t)(l0 + r) * RS + c);
        *(uint2*)(smem + QO + swz(r, c * 2)) = pack4h(x);
    }
    #pragma unroll
    for (int i = 0; i < 4; i++) {
        int e4 = i * THREADS + tid;
        int r = e4 >> 4, c = (e4 & 15) << 2;
        float4 xk = *(const float4*)(kb + (size_t)r * RS + c);
        *(uint2*)(smem + KO(0) + swz(r, c * 2)) = pack4h(xk);
        float4 xv = *(const float4*)(vb + (size_t)r * RS + c);
        *(uint2*)(smem + VO(0) + swz(r, c * 2)) = pack4h(xv);
    }

    float O[2][8][4];
    #pragma unroll
    for (int mb = 0; mb < 2; mb++)
        #pragma unroll
        for (int nb = 0; nb < 8; nb++) {
            O[mb][nb][0] = 0.f; O[mb][nb][1] = 0.f; O[mb][nb][2] = 0.f; O[mb][nb][3] = 0.f;
        }
    float ls[4] = {0.f, 0.f, 0.f, 0.f};

    const int ldr = tid >> 4;                // 0..15
    const int ldc = (tid & 15) << 2;         // 0..60 step 4

    for (int st = 0; st < NT; st++) {
        __syncthreads();     // tiles in buf visible; buf^1 free for overwrite
        const int buf = st & 1;

        // prefetch next K into regs
        float4 kq[4];
        if (st < NT - 1) {
            const int s0n = (st + 1) * BN;
            #pragma unroll
            for (int i = 0; i < 4; i++)
                kq[i] = *(const float4*)(kb + (size_t)(s0n + i * 16 + ldr) * RS + ldc);
        }

        uint32_t P[2][2][4];     // fp16 A-frags for PV (this warp's 32x32 P block)

        // ---- S + softmax, per 16-col group (kb2) ----
        #pragma unroll
        for (int kb2 = 0; kb2 < 2; kb2++) {
            float S[2][2][4];
            #pragma unroll
            for (int mb = 0; mb < 2; mb++)
                #pragma unroll
                for (int ns = 0; ns < 2; ns++) {
                    S[mb][ns][0] = 0.f; S[mb][ns][1] = 0.f; S[mb][ns][2] = 0.f; S[mb][ns][3] = 0.f;
                }
            #pragma unroll
            for (int kbk = 0; kbk < 4; kbk++) {
                uint32_t Kf0, Kf1, Kf2, Kf3;
                {
                    int rk = 32 * nw + 16 * kb2 + (lane & 7) + ((lane & 16) >> 1);
                    int cbk = kbk * 32 + (((lane >> 3) & 1) << 4);
                    LDSM4(Kf0, Kf1, Kf2, Kf3, sb + KO(buf) + swz(rk, cbk));
                }
                #pragma unroll
                for (int mb = 0; mb < 2; mb++) {
                    uint32_t Qf0, Qf1, Qf2, Qf3;
                    LDSM4(Qf0, Qf1, Qf2, Qf3,
                          sb + QO + swz(32 * mw + 16 * mb + (lane & 15),
                                        kbk * 32 + ((lane >> 4) << 4)));
                    MMA16816(S[mb][0], Qf0, Qf1, Qf2, Qf3, Kf0, Kf1);
                    MMA16816(S[mb][1], Qf0, Qf1, Qf2, Qf3, Kf2, Kf3);
                }
            }
            // softmax: p = exp2(s * w'), w' has log2e folded; |z|<<1 -> no max
            #pragma unroll
            for (int mb = 0; mb < 2; mb++) {
                const float* wr = g_w + (size_t)(l0 + 32 * mw + 16 * mb + g) * L_SZ
                                  + st * BN + 32 * nw + 16 * kb2 + 2 * t4;
                #pragma unroll
                for (int ns = 0; ns < 2; ns++) {
                    float2 wa = *(const float2*)(wr + ns * 8);
                    float2 wb = *(const float2*)(wr + ns * 8 + 8 * L_SZ);
                    float e0 = ex2f(S[mb][ns][0] * wa.x);
                    float e1 = ex2f(S[mb][ns][1] * wa.y);
                    float e2 = ex2f(S[mb][ns][2] * wb.x);
                    float e3 = ex2f(S[mb][ns][3] * wb.y);
                    ls[mb * 2 + 0] += e0 + e1;
                    ls[mb * 2 + 1] += e2 + e3;
                    half2 h0 = __floats2half2_rn(e0, e1);
                    half2 h1 = __floats2half2_rn(e2, e3);
                    P[mb][kb2][ns * 2]     = *(uint32_t*)&h0;   // a0 / a2
                    P[mb][kb2][ns * 2 + 1] = *(uint32_t*)&h1;   // a1 / a3
                }
            }
        }

        // store next K; prefetch next V
        float4 vq[4];
        if (st < NT - 1) {
            #pragma unroll
            for (int i = 0; i < 4; i++)
                *(uint2*)(smem + KO(buf ^ 1) + swz(i * 16 + ldr, ldc * 2)) = pack4h(kq[i]);
            const int s0n = (st + 1) * BN;
            #pragma unroll
            for (int i = 0; i < 4; i++)
                vq[i] = *(const float4*)(vb + (size_t)(s0n + i * 16 + ldr) * RS + ldc);
        }

        // ---- O_partial += P * V (k-rows 32*nw..+31) ----
        #pragma unroll
        for (int kb2 = 0; kb2 < 2; kb2++) {
            uint32_t Vf[4][4];
            #pragma unroll
            for (int n16 = 0; n16 < 4; n16++) {
                int rv = 32 * nw + 16 * kb2 + (lane & 15);
                int cbv = n16 * 32 + ((lane >> 4) << 4);
                LDSM4T(Vf[n16][0], Vf[n16][1], Vf[n16][2], Vf[n16][3],
                       sb + VO(buf) + swz(rv, cbv));
            }
            #pragma unroll
            for (int mb = 0; mb < 2; mb++)
                #pragma unroll
                for (int nb = 0; nb < 8; nb++)
                    MMA16816(O[mb][nb], P[mb][kb2][0], P[mb][kb2][1], P[mb][kb2][2], P[mb][kb2][3],
                             Vf[nb >> 1][(nb & 1) * 2], Vf[nb >> 1][(nb & 1) * 2 + 1]);
        }

        // store next V
        if (st < NT - 1) {
            #pragma unroll
            for (int i = 0; i < 4; i++)
                *(uint2*)(smem + VO(buf ^ 1) + swz(i * 16 + ldr, ldc * 2)) = pack4h(vq[i]);
        }
    }

    // ---- epilogue: combine k-halves (nw 0/1) and row sums, store ----
    __syncthreads();    // all PV reads done; smem reusable

    #pragma unroll
    for (int j = 0; j < 4; j++) {
        ls[j] += __shfl_xor_sync(0xffffffffu, ls[j], 1);
        ls[j] += __shfl_xor_sync(0xffffffffu, ls[j], 2);
    }
    float* LS = (float*)(smem + LSO);
    if (t4 == 0) {
        #pragma unroll
        for (int mb = 0; mb < 2; mb++)
            #pragma unroll
            for (int hf = 0; hf < 2; hf++)
                LS[(32 * mw + 16 * mb + 8 * hf + g) * 2 + nw] = ls[mb * 2 + hf];
    }
    float* OB = (float*)smem;    // 128 x OBS scratch (overlaps dead Q/K tiles)
    if (nw == 0) {
        #pragma unroll
        for (int mb = 0; mb < 2; mb++) {
            int r = 32 * mw + 16 * mb + g;
            #pragma unroll
            for (int nb = 0; nb < 8; nb++) {
                int c = 8 * nb + 2 * t4;
                *(float2*)(OB + r * OBS + c) = make_float2(O[mb][nb][0], O[mb][nb][1]);
                *(float2*)(OB + (r + 8) * OBS + c) = make_float2(O[mb][nb][2], O[mb][nb][3]);
            }
        }
    }
    __syncthreads();
    if (nw == 1) {
        #pragma unroll
        for (int mb = 0; mb < 2; mb++) {
            int r = 32 * mw + 16 * mb + g;
            float inv0 = 1.f / (LS[r * 2] + LS[r * 2 + 1]);
            float inv1 = 1.f / (LS[(r + 8) * 2] + LS[(r + 8) * 2 + 1]);
            #pragma unroll
            for (int nb = 0; nb < 8; nb++) {
                int c = 8 * nb + 2 * t4;
                float2 p0 = *(float2*)(OB + r * OBS + c);
                float2 p1 = *(float2*)(OB + (r + 8) * OBS + c);
                *(float2*)(ob + (size_t)(l0 + r) * RS + c) =
                    make_float2((O[mb][nb][0] + p0.x) * inv0, (O[mb][nb][1] + p0.y) * inv0);
                *(float2*)(ob + (size_t)(l0 + r + 8) * RS + c) =
                    make_float2((O[mb][nb][2] + p1.x) * inv1, (O[mb][nb][3] + p1.y) * inv1);
            }
        }
    }
}

// ---------------- launcher ----------------
extern "C" void kernel_launch(void* const* d_in, const int* in_sizes, int n_in,
                              void* d_out, int out_size) {
    const float* q   = (const float*)d_in[0];
    const float* k   = (const float*)d_in[1];
    const float* v   = (const float*)d_in[2];
    const float* wm  = (const float*)d_in[3];
    const float* tau = (const float*)d_in[4];
    // d_in[5] = attn_mask, unused (mask_flag=False)

    cudaFuncSetAttribute(flash_kernel, cudaFuncAttributeMaxDynamicSharedMemorySize, SMEM_BYTES);

    wprep_kernel<<<L_SZ, 256>>>(wm, tau);

    dim3 grid(L_SZ / BM, B_SZ * H_SZ);
    flash_kernel<<<grid, THREADS, SMEM_BYTES>>>(q, k, v, (float*)d_out);
}

// round 8
// speedup vs baseline: 1.7148x; 1.7123x over previous
#include <cuda_runtime.h>
#include <cuda_fp16.h>
#include <cstdint>
#include <math.h>

// ---------------- problem constants ----------------
#define B_SZ 16
#define H_SZ 8
#define L_SZ 1024
#define E_SZ 64
#define RS   512                 // floats between consecutive rows (H*E)

#define BM 128
#define BN 64
#define NT 16
#define THREADS 256

// ---------------- smem byte map (fp16 tiles, 128B swizzled rows) ------------
#define QO   0                       // 128 x 64 fp16 = 16 KB
#define KO(b) (16384 + (b) * 8192)   // 64 x 64 fp16, double buffered
#define VO(b) (32768 + (b) * 8192)
#define LSO  49152                   // 128 x 2 fp32 partial row sums
#define SMEM_BYTES 50176
#define OBS  66                      // epilogue O-buffer row stride (floats)

// g_w[l][s] = softmax_s(wm[l][s]/softplus(tau[l])) * (1/8) * log2(e)
__device__ float g_w[L_SZ * L_SZ];

// ---------------- helpers ----------------
__device__ __forceinline__ uint32_t smem_u32(const void* p) {
    uint32_t a;
    asm("{ .reg .u64 t; cvta.to.shared.u64 t, %1; cvt.u32.u64 %0, t; }" : "=r"(a) : "l"(p));
    return a;
}
// 128B-row XOR swizzle
__device__ __forceinline__ uint32_t swz(int r, int cb) {
    return (uint32_t)(r * 128 + (cb ^ ((r & 7) << 4)));
}
__device__ __forceinline__ float ex2f(float x) {
    float y; asm("ex2.approx.f32 %0, %1;" : "=f"(y) : "f"(x)); return y;
}

#define LDSM4(d0,d1,d2,d3,a) \
    asm volatile("ldmatrix.sync.aligned.m8n8.x4.shared.b16 {%0,%1,%2,%3}, [%4];" \
        : "=r"(d0),"=r"(d1),"=r"(d2),"=r"(d3) : "r"(a))
#define LDSM4T(d0,d1,d2,d3,a) \
    asm volatile("ldmatrix.sync.aligned.m8n8.x4.trans.shared.b16 {%0,%1,%2,%3}, [%4];" \
        : "=r"(d0),"=r"(d1),"=r"(d2),"=r"(d3) : "r"(a))
#define MMA16816(c, a0,a1,a2,a3, b0,b1) \
    asm volatile("mma.sync.aligned.m16n8k16.row.col.f32.f16.f16.f32 " \
        "{%0,%1,%2,%3},{%4,%5,%6,%7},{%8,%9},{%0,%1,%2,%3};" \
        : "+f"((c)[0]),"+f"((c)[1]),"+f"((c)[2]),"+f"((c)[3]) \
        : "r"(a0),"r"(a1),"r"(a2),"r"(a3),"r"(b0),"r"(b1))

__device__ __forceinline__ uint2 pack4h(float4 x) {
    half2 h0 = __floats2half2_rn(x.x, x.y);
    half2 h1 = __floats2half2_rn(x.z, x.w);
    return make_uint2(*(uint32_t*)&h0, *(uint32_t*)&h1);
}

// ---------------- kernel 1: modulation weights ----------------
__global__ void wprep_kernel(const float* __restrict__ wm, const float* __restrict__ tau) {
    __shared__ float red_m[8];
    __shared__ float red_s[8];
    const int row = blockIdx.x, tid = threadIdx.x;
    const int warp = tid >> 5, lane = tid & 31;

    float t = tau[row];
    float sp = (t > 20.f) ? t : log1pf(__expf(t));
    float inv = 1.f / sp;

    float4 x = reinterpret_cast<const float4*>(wm + (size_t)row * L_SZ)[tid];
    x.x *= inv; x.y *= inv; x.z *= inv; x.w *= inv;

    float mx = fmaxf(fmaxf(x.x, x.y), fmaxf(x.z, x.w));
    #pragma unroll
    for (int o = 16; o; o >>= 1) mx = fmaxf(mx, __shfl_xor_sync(0xffffffffu, mx, o));
    if (lane == 0) red_m[warp] = mx;
    __syncthreads();
    float M = red_m[0];
    #pragma unroll
    for (int i = 1; i < 8; i++) M = fmaxf(M, red_m[i]);

    float e0 = __expf(x.x - M), e1 = __expf(x.y - M);
    float e2 = __expf(x.z - M), e3 = __expf(x.w - M);
    float s = e0 + e1 + e2 + e3;
    #pragma unroll
    for (int o = 16; o; o >>= 1) s += __shfl_xor_sync(0xffffffffu, s, o);
    if (lane == 0) red_s[warp] = s;
    __syncthreads();
    float S = 0.f;
    #pragma unroll
    for (int i = 0; i < 8; i++) S += red_s[i];

    float f = 0.125f / S * 1.44269504089f;   // fold 1/sqrt(E) and log2(e)
    reinterpret_cast<float4*>(g_w + (size_t)row * L_SZ)[tid] =
        make_float4(e0 * f, e1 * f, e2 * f, e3 * f);
}

// -------- kernel 2: fp16 mma flash attention, register-P, k-split PV --------
__global__ void __launch_bounds__(THREADS, 1)
flash_kernel(const float* __restrict__ q, const float* __restrict__ kmat,
             const float* __restrict__ v, float* __restrict__ out) {
    extern __shared__ char smem[];
    const uint32_t sb = smem_u32(smem);

    const int tid = threadIdx.x;
    const int warp = tid >> 5, lane = tid & 31;
    const int mw = warp >> 1, nw = warp & 1;     // 4 M-warps x 2 K-split warps
    const int g = lane >> 2, t4 = lane & 3;
    const int l0 = blockIdx.x * BM;

    const size_t base = (size_t)(blockIdx.y >> 3) * (L_SZ * RS) + (size_t)(blockIdx.y & 7) * E_SZ;
    const float* qb = q + base;
    const float* kb = kmat + base;
    const float* vb = v + base;
    float* ob = out + base;

    // ---- prologue: stage Q / K0 / V0 as swizzled fp16 ----
    #pragma unroll
    for (int i = 0; i < 8; i++) {
        int e4 = i * THREADS + tid;
        int r = e4 >> 4, c = (e4 & 15) << 2;
        float4 x = *(const float4*)(qb + (size_t)(l0 + r) * RS + c);
        *(uint2*)(smem + QO + swz(r, c * 2)) = pack4h(x);
    }
    #pragma unroll
    for (int i = 0; i < 4; i++) {
        int e4 = i * THREADS + tid;
        int r = e4 >> 4, c = (e4 & 15) << 2;
        float4 xk = *(const float4*)(kb + (size_t)r * RS + c);
        *(uint2*)(smem + KO(0) + swz(r, c * 2)) = pack4h(xk);
        float4 xv = *(const float4*)(vb + (size_t)r * RS + c);
        *(uint2*)(smem + VO(0) + swz(r, c * 2)) = pack4h(xv);
    }
    __syncthreads();

    // ---- persistent Q fragments (rows 32*mw..+31, k=0..63): 32 regs ----
    uint32_t QA[2][4][4];
    #pragma unroll
    for (int mb = 0; mb < 2; mb++)
        #pragma unroll
        for (int kbk = 0; kbk < 4; kbk++)
            LDSM4(QA[mb][kbk][0], QA[mb][kbk][1], QA[mb][kbk][2], QA[mb][kbk][3],
                  sb + QO + swz(32 * mw + 16 * mb + (lane & 15),
                                kbk * 32 + ((lane >> 4) << 4)));

    float O[2][8][4];
    #pragma unroll
    for (int mb = 0; mb < 2; mb++)
        #pragma unroll
        for (int nb = 0; nb < 8; nb++) {
            O[mb][nb][0] = 0.f; O[mb][nb][1] = 0.f; O[mb][nb][2] = 0.f; O[mb][nb][3] = 0.f;
        }
    float ls[4] = {0.f, 0.f, 0.f, 0.f};

    const int ldr = tid >> 4;                // 0..15
    const int ldc = (tid & 15) << 2;         // 0..60 step 4

    for (int st = 0; st < NT; st++) {
        if (st) __syncthreads();   // new tiles visible; buf^1 free (st=0 covered above)
        const int buf = st & 1;

        // prefetch next K into regs
        float4 kq[4];
        if (st < NT - 1) {
            const int s0n = (st + 1) * BN;
            #pragma unroll
            for (int i = 0; i < 4; i++)
                kq[i] = *(const float4*)(kb + (size_t)(s0n + i * 16 + ldr) * RS + ldc);
        }

        uint32_t P[2][2][4];     // fp16 A-frags for PV (this warp's 32x32 P block)

        // ---- S + softmax, per 16-col group (kb2) ----
        #pragma unroll
        for (int kb2 = 0; kb2 < 2; kb2++) {
            float S[2][2][4];
            #pragma unroll
            for (int mb = 0; mb < 2; mb++)
                #pragma unroll
                for (int ns = 0; ns < 2; ns++) {
                    S[mb][ns][0] = 0.f; S[mb][ns][1] = 0.f; S[mb][ns][2] = 0.f; S[mb][ns][3] = 0.f;
                }
            #pragma unroll
            for (int kbk = 0; kbk < 4; kbk++) {
                uint32_t Kf0, Kf1, Kf2, Kf3;
                {
                    int rk = 32 * nw + 16 * kb2 + (lane & 7) + ((lane & 16) >> 1);
                    int cbk = kbk * 32 + (((lane >> 3) & 1) << 4);
                    LDSM4(Kf0, Kf1, Kf2, Kf3, sb + KO(buf) + swz(rk, cbk));
                }
                #pragma unroll
                for (int mb = 0; mb < 2; mb++) {
                    MMA16816(S[mb][0], QA[mb][kbk][0], QA[mb][kbk][1], QA[mb][kbk][2], QA[mb][kbk][3],
                             Kf0, Kf1);
                    MMA16816(S[mb][1], QA[mb][kbk][0], QA[mb][kbk][1], QA[mb][kbk][2], QA[mb][kbk][3],
                             Kf2, Kf3);
                }
            }
            // softmax: p = exp2(s * w'), w' has log2e folded; |z|<<1 -> no max
            #pragma unroll
            for (int mb = 0; mb < 2; mb++) {
                const float* wr = g_w + (size_t)(l0 + 32 * mw + 16 * mb + g) * L_SZ
                                  + st * BN + 32 * nw + 16 * kb2 + 2 * t4;
                #pragma unroll
                for (int ns = 0; ns < 2; ns++) {
                    float2 wa = *(const float2*)(wr + ns * 8);
                    float2 wb = *(const float2*)(wr + ns * 8 + 8 * L_SZ);
                    float e0 = ex2f(S[mb][ns][0] * wa.x);
                    float e1 = ex2f(S[mb][ns][1] * wa.y);
                    float e2 = ex2f(S[mb][ns][2] * wb.x);
                    float e3 = ex2f(S[mb][ns][3] * wb.y);
                    ls[mb * 2 + 0] += e0 + e1;
                    ls[mb * 2 + 1] += e2 + e3;
                    half2 h0 = __floats2half2_rn(e0, e1);
                    half2 h1 = __floats2half2_rn(e2, e3);
                    P[mb][kb2][ns * 2]     = *(uint32_t*)&h0;   // a0 / a2
                    P[mb][kb2][ns * 2 + 1] = *(uint32_t*)&h1;   // a1 / a3
                }
            }
        }

        // store next K; prefetch next V
        float4 vq[4];
        if (st < NT - 1) {
            #pragma unroll
            for (int i = 0; i < 4; i++)
                *(uint2*)(smem + KO(buf ^ 1) + swz(i * 16 + ldr, ldc * 2)) = pack4h(kq[i]);
            const int s0n = (st + 1) * BN;
            #pragma unroll
            for (int i = 0; i < 4; i++)
                vq[i] = *(const float4*)(vb + (size_t)(s0n + i * 16 + ldr) * RS + ldc);
        }

        // ---- O_partial += P * V (k-rows 32*nw..+31) ----
        #pragma unroll
        for (int kb2 = 0; kb2 < 2; kb2++) {
            uint32_t Vf[4][4];
            #pragma unroll
            for (int n16 = 0; n16 < 4; n16++) {
                int rv = 32 * nw + 16 * kb2 + (lane & 15);
                int cbv = n16 * 32 + ((lane >> 4) << 4);
                LDSM4T(Vf[n16][0], Vf[n16][1], Vf[n16][2], Vf[n16][3],
                       sb + VO(buf) + swz(rv, cbv));
            }
            #pragma unroll
            for (int mb = 0; mb < 2; mb++)
                #pragma unroll
                for (int nb = 0; nb < 8; nb++)
                    MMA16816(O[mb][nb], P[mb][kb2][0], P[mb][kb2][1], P[mb][kb2][2], P[mb][kb2][3],
                             Vf[nb >> 1][(nb & 1) * 2], Vf[nb >> 1][(nb & 1) * 2 + 1]);
        }

        // store next V
        if (st < NT - 1) {
            #pragma unroll
            for (int i = 0; i < 4; i++)
                *(uint2*)(smem + VO(buf ^ 1) + swz(i * 16 + ldr, ldc * 2)) = pack4h(vq[i]);
        }
    }

    // ---- epilogue: combine k-halves (nw 0/1) and row sums, store ----
    __syncthreads();    // all PV reads done; smem reusable

    #pragma unroll
    for (int j = 0; j < 4; j++) {
        ls[j] += __shfl_xor_sync(0xffffffffu, ls[j], 1);
        ls[j] += __shfl_xor_sync(0xffffffffu, ls[j], 2);
    }
    float* LS = (float*)(smem + LSO);
    if (t4 == 0) {
        #pragma unroll
        for (int mb = 0; mb < 2; mb++)
            #pragma unroll
            for (int hf = 0; hf < 2; hf++)
                LS[(32 * mw + 16 * mb + 8 * hf + g) * 2 + nw] = ls[mb * 2 + hf];
    }
    float* OB = (float*)smem;    // 128 x OBS scratch (overlaps dead Q/K tiles)
    if (nw == 0) {
        #pragma unroll
        for (int mb = 0; mb < 2; mb++) {
            int r = 32 * mw + 16 * mb + g;
            #pragma unroll
            for (int nb = 0; nb < 8; nb++) {
                int c = 8 * nb + 2 * t4;
                *(float2*)(OB + r * OBS + c) = make_float2(O[mb][nb][0], O[mb][nb][1]);
                *(float2*)(OB + (r + 8) * OBS + c) = make_float2(O[mb][nb][2], O[mb][nb][3]);
            }
        }
    }
    __syncthreads();
    if (nw == 1) {
        #pragma unroll
        for (int mb = 0; mb < 2; mb++) {
            int r = 32 * mw + 16 * mb + g;
            float inv0 = 1.f / (LS[r * 2] + LS[r * 2 + 1]);
            float inv1 = 1.f / (LS[(r + 8) * 2] + LS[(r + 8) * 2 + 1]);
            #pragma unroll
            for (int nb = 0; nb < 8; nb++) {
                int c = 8 * nb + 2 * t4;
                float2 p0 = *(float2*)(OB + r * OBS + c);
                float2 p1 = *(float2*)(OB + (r + 8) * OBS + c);
                *(float2*)(ob + (size_t)(l0 + r) * RS + c) =
                    make_float2((O[mb][nb][0] + p0.x) * inv0, (O[mb][nb][1] + p0.y) * inv0);
                *(float2*)(ob + (size_t)(l0 + r + 8) * RS + c) =
                    make_float2((O[mb][nb][2] + p1.x) * inv1, (O[mb][nb][3] + p1.y) * inv1);
            }
        }
    }
}

// ---------------- launcher ----------------
extern "C" void kernel_launch(void* const* d_in, const int* in_sizes, int n_in,
                              void* d_out, int out_size) {
    const float* q   = (const float*)d_in[0];
    const float* k   = (const float*)d_in[1];
    const float* v   = (const float*)d_in[2];
    const float* wm  = (const float*)d_in[3];
    const float* tau = (const float*)d_in[4];
    // d_in[5] = attn_mask, unused (mask_flag=False)

    cudaFuncSetAttribute(flash_kernel, cudaFuncAttributeMaxDynamicSharedMemorySize, SMEM_BYTES);

    wprep_kernel<<<L_SZ, 256>>>(wm, tau);

    dim3 grid(L_SZ / BM, B_SZ * H_SZ);
    flash_kernel<<<grid, THREADS, SMEM_BYTES>>>(q, k, v, (float*)d_out);
}

// round 9
// speedup vs baseline: 1.8070x; 1.0538x over previous
#include <cuda_runtime.h>
#include <cuda_fp16.h>
#include <cstdint>
#include <math.h>

// ---------------- problem constants ----------------
#define B_SZ 16
#define H_SZ 8
#define L_SZ 1024
#define E_SZ 64
#define RS   512                 // floats between consecutive rows (H*E)

#define BM 128
#define BN 64
#define NT 16
#define THREADS 512

// ---------------- smem byte map (fp16 tiles, 128B swizzled rows) ------------
#define QO   0                       // 128 x 64 fp16 = 16 KB
#define KO(b) (16384 + (b) * 8192)   // 64 x 64 fp16, double buffered
#define VO(b) (32768 + (b) * 8192)
#define LSO  49152                   // 128 x 2 fp32 partial row sums
#define SMEM_BYTES 50176
#define OBS  66                      // epilogue O-buffer row stride (floats)

// g_w[l][s] = softmax_s(wm[l][s]/softplus(tau[l])) * (1/8) * log2(e)
__device__ float g_w[L_SZ * L_SZ];

// ---------------- helpers ----------------
__device__ __forceinline__ uint32_t smem_u32(const void* p) {
    uint32_t a;
    asm("{ .reg .u64 t; cvta.to.shared.u64 t, %1; cvt.u32.u64 %0, t; }" : "=r"(a) : "l"(p));
    return a;
}
// 128B-row XOR swizzle
__device__ __forceinline__ uint32_t swz(int r, int cb) {
    return (uint32_t)(r * 128 + (cb ^ ((r & 7) << 4)));
}
__device__ __forceinline__ float ex2f(float x) {
    float y; asm("ex2.approx.f32 %0, %1;" : "=f"(y) : "f"(x)); return y;
}

#define LDSM4(d0,d1,d2,d3,a) \
    asm volatile("ldmatrix.sync.aligned.m8n8.x4.shared.b16 {%0,%1,%2,%3}, [%4];" \
        : "=r"(d0),"=r"(d1),"=r"(d2),"=r"(d3) : "r"(a))
#define LDSM4T(d0,d1,d2,d3,a) \
    asm volatile("ldmatrix.sync.aligned.m8n8.x4.trans.shared.b16 {%0,%1,%2,%3}, [%4];" \
        : "=r"(d0),"=r"(d1),"=r"(d2),"=r"(d3) : "r"(a))
#define MMA16816(c, a0,a1,a2,a3, b0,b1) \
    asm volatile("mma.sync.aligned.m16n8k16.row.col.f32.f16.f16.f32 " \
        "{%0,%1,%2,%3},{%4,%5,%6,%7},{%8,%9},{%0,%1,%2,%3};" \
        : "+f"((c)[0]),"+f"((c)[1]),"+f"((c)[2]),"+f"((c)[3]) \
        : "r"(a0),"r"(a1),"r"(a2),"r"(a3),"r"(b0),"r"(b1))

__device__ __forceinline__ uint2 pack4h(float4 x) {
    half2 h0 = __floats2half2_rn(x.x, x.y);
    half2 h1 = __floats2half2_rn(x.z, x.w);
    return make_uint2(*(uint32_t*)&h0, *(uint32_t*)&h1);
}

// ---------------- kernel 1: modulation weights ----------------
__global__ void wprep_kernel(const float* __restrict__ wm, const float* __restrict__ tau) {
    __shared__ float red_m[8];
    __shared__ float red_s[8];
    const int row = blockIdx.x, tid = threadIdx.x;
    const int warp = tid >> 5, lane = tid & 31;

    float t = tau[row];
    float sp = (t > 20.f) ? t : log1pf(__expf(t));
    float inv = 1.f / sp;

    float4 x = reinterpret_cast<const float4*>(wm + (size_t)row * L_SZ)[tid];
    x.x *= inv; x.y *= inv; x.z *= inv; x.w *= inv;

    float mx = fmaxf(fmaxf(x.x, x.y), fmaxf(x.z, x.w));
    #pragma unroll
    for (int o = 16; o; o >>= 1) mx = fmaxf(mx, __shfl_xor_sync(0xffffffffu, mx, o));
    if (lane == 0) red_m[warp] = mx;
    __syncthreads();
    float M = red_m[0];
    #pragma unroll
    for (int i = 1; i < 8; i++) M = fmaxf(M, red_m[i]);

    float e0 = __expf(x.x - M), e1 = __expf(x.y - M);
    float e2 = __expf(x.z - M), e3 = __expf(x.w - M);
    float s = e0 + e1 + e2 + e3;
    #pragma unroll
    for (int o = 16; o; o >>= 1) s += __shfl_xor_sync(0xffffffffu, s, o);
    if (lane == 0) red_s[warp] = s;
    __syncthreads();
    float S = 0.f;
    #pragma unroll
    for (int i = 0; i < 8; i++) S += red_s[i];

    float f = 0.125f / S * 1.44269504089f;   // fold 1/sqrt(E) and log2(e)
    reinterpret_cast<float4*>(g_w + (size_t)row * L_SZ)[tid] =
        make_float4(e0 * f, e1 * f, e2 * f, e3 * f);
}

// ------ kernel 2: fp16 mma flash attention, 16 warps, register-P, k-split ---
__global__ void __launch_bounds__(THREADS, 1)
flash_kernel(const float* __restrict__ q, const float* __restrict__ kmat,
             const float* __restrict__ v, float* __restrict__ out) {
    extern __shared__ char smem[];
    const uint32_t sb = smem_u32(smem);

    const int tid = threadIdx.x;
    const int warp = tid >> 5, lane = tid & 31;
    const int mw = warp >> 1, nw = warp & 1;     // 8 M-warps x 2 K-split warps
    const int g = lane >> 2, t4 = lane & 3;
    const int l0 = blockIdx.x * BM;

    const size_t base = (size_t)(blockIdx.y >> 3) * (L_SZ * RS) + (size_t)(blockIdx.y & 7) * E_SZ;
    const float* qb = q + base;
    const float* kb = kmat + base;
    const float* vb = v + base;
    float* ob = out + base;

    // ---- prologue: stage Q / K0 / V0 as swizzled fp16 ----
    #pragma unroll
    for (int i = 0; i < 4; i++) {
        int e4 = i * THREADS + tid;              // 2048 float4
        int r = e4 >> 4, c = (e4 & 15) << 2;
        float4 x = *(const float4*)(qb + (size_t)(l0 + r) * RS + c);
        *(uint2*)(smem + QO + swz(r, c * 2)) = pack4h(x);
    }
    #pragma unroll
    for (int i = 0; i < 2; i++) {
        int e4 = i * THREADS + tid;              // 1024 float4
        int r = e4 >> 4, c = (e4 & 15) << 2;
        float4 xk = *(const float4*)(kb + (size_t)r * RS + c);
        *(uint2*)(smem + KO(0) + swz(r, c * 2)) = pack4h(xk);
        float4 xv = *(const float4*)(vb + (size_t)r * RS + c);
        *(uint2*)(smem + VO(0) + swz(r, c * 2)) = pack4h(xv);
    }
    __syncthreads();

    // ---- persistent Q fragments (rows 16*mw..+15, k=0..63): 16 regs ----
    uint32_t QA[4][4];
    #pragma unroll
    for (int kbk = 0; kbk < 4; kbk++)
        LDSM4(QA[kbk][0], QA[kbk][1], QA[kbk][2], QA[kbk][3],
              sb + QO + swz(16 * mw + (lane & 15), kbk * 32 + ((lane >> 4) << 4)));

    float O[8][4];
    #pragma unroll
    for (int nb = 0; nb < 8; nb++) {
        O[nb][0] = 0.f; O[nb][1] = 0.f; O[nb][2] = 0.f; O[nb][3] = 0.f;
    }
    float ls[2] = {0.f, 0.f};

    const int ldr = tid >> 4;                // 0..31
    const int ldc = (tid & 15) << 2;         // 0..60 step 4

    for (int st = 0; st < NT; st++) {
        if (st) __syncthreads();   // new tiles visible; buf^1 free
        const int buf = st & 1;

        // prefetch next K into regs (2 float4)
        float4 kq[2];
        if (st < NT - 1) {
            const int s0n = (st + 1) * BN;
            #pragma unroll
            for (int i = 0; i < 2; i++)
                kq[i] = *(const float4*)(kb + (size_t)(s0n + i * 32 + ldr) * RS + ldc);
        }

        uint32_t P[2][4];     // fp16 A-frags for PV (this warp's 16x32 P block)

        // ---- S + softmax, per 16-col group (kb2) ----
        #pragma unroll
        for (int kb2 = 0; kb2 < 2; kb2++) {
            float S[2][4];
            #pragma unroll
            for (int ns = 0; ns < 2; ns++) {
                S[ns][0] = 0.f; S[ns][1] = 0.f; S[ns][2] = 0.f; S[ns][3] = 0.f;
            }
            #pragma unroll
            for (int kbk = 0; kbk < 4; kbk++) {
                uint32_t Kf0, Kf1, Kf2, Kf3;
                {
                    int rk = 32 * nw + 16 * kb2 + (lane & 7) + ((lane & 16) >> 1);
                    int cbk = kbk * 32 + (((lane >> 3) & 1) << 4);
                    LDSM4(Kf0, Kf1, Kf2, Kf3, sb + KO(buf) + swz(rk, cbk));
                }
                MMA16816(S[0], QA[kbk][0], QA[kbk][1], QA[kbk][2], QA[kbk][3], Kf0, Kf1);
                MMA16816(S[1], QA[kbk][0], QA[kbk][1], QA[kbk][2], QA[kbk][3], Kf2, Kf3);
            }
            // softmax: p = exp2(s * w'), w' has log2e folded; |z|<<1 -> no max
            const float* wr = g_w + (size_t)(l0 + 16 * mw + g) * L_SZ
                              + st * BN + 32 * nw + 16 * kb2 + 2 * t4;
            #pragma unroll
            for (int ns = 0; ns < 2; ns++) {
                float2 wa = *(const float2*)(wr + ns * 8);
                float2 wb = *(const float2*)(wr + ns * 8 + 8 * L_SZ);
                float e0 = ex2f(S[ns][0] * wa.x);
                float e1 = ex2f(S[ns][1] * wa.y);
                float e2 = ex2f(S[ns][2] * wb.x);
                float e3 = ex2f(S[ns][3] * wb.y);
                ls[0] += e0 + e1;
                ls[1] += e2 + e3;
                half2 h0 = __floats2half2_rn(e0, e1);
                half2 h1 = __floats2half2_rn(e2, e3);
                P[kb2][ns * 2]     = *(uint32_t*)&h0;   // a0 / a2
                P[kb2][ns * 2 + 1] = *(uint32_t*)&h1;   // a1 / a3
            }
        }

        // store next K; prefetch next V
        float4 vq[2];
        if (st < NT - 1) {
            #pragma unroll
            for (int i = 0; i < 2; i++)
                *(uint2*)(smem + KO(buf ^ 1) + swz(i * 32 + ldr, ldc * 2)) = pack4h(kq[i]);
            const int s0n = (st + 1) * BN;
            #pragma unroll
            for (int i = 0; i < 2; i++)
                vq[i] = *(const float4*)(vb + (size_t)(s0n + i * 32 + ldr) * RS + ldc);
        }

        // ---- O_partial += P * V (k-rows 32*nw..+31) ----
        #pragma unroll
        for (int kb2 = 0; kb2 < 2; kb2++) {
            uint32_t Vf[4][4];
            #pragma unroll
            for (int n16 = 0; n16 < 4; n16++) {
                int rv = 32 * nw + 16 * kb2 + (lane & 15);
                int cbv = n16 * 32 + ((lane >> 4) << 4);
                LDSM4T(Vf[n16][0], Vf[n16][1], Vf[n16][2], Vf[n16][3],
                       sb + VO(buf) + swz(rv, cbv));
            }
            #pragma unroll
            for (int nb = 0; nb < 8; nb++)
                MMA16816(O[nb], P[kb2][0], P[kb2][1], P[kb2][2], P[kb2][3],
                         Vf[nb >> 1][(nb & 1) * 2], Vf[nb >> 1][(nb & 1) * 2 + 1]);
        }

        // store next V
        if (st < NT - 1) {
            #pragma unroll
            for (int i = 0; i < 2; i++)
                *(uint2*)(smem + VO(buf ^ 1) + swz(i * 32 + ldr, ldc * 2)) = pack4h(vq[i]);
        }
    }

    // ---- epilogue: combine k-halves (nw 0/1) and row sums, store ----
    __syncthreads();    // all PV reads done; smem reusable

    ls[0] += __shfl_xor_sync(0xffffffffu, ls[0], 1);
    ls[0] += __shfl_xor_sync(0xffffffffu, ls[0], 2);
    ls[1] += __shfl_xor_sync(0xffffffffu, ls[1], 1);
    ls[1] += __shfl_xor_sync(0xffffffffu, ls[1], 2);

    float* LS = (float*)(smem + LSO);
    if (t4 == 0) {
        LS[(16 * mw + g) * 2 + nw]     = ls[0];
        LS[(16 * mw + 8 + g) * 2 + nw] = ls[1];
    }
    float* OB = (float*)smem;    // 128 x OBS scratch (overlaps dead Q/K tiles)
    if (nw == 0) {
        int r = 16 * mw + g;
        #pragma unroll
        for (int nb = 0; nb < 8; nb++) {
            int c = 8 * nb + 2 * t4;
            *(float2*)(OB + r * OBS + c) = make_float2(O[nb][0], O[nb][1]);
            *(float2*)(OB + (r + 8) * OBS + c) = make_float2(O[nb][2], O[nb][3]);
        }
    }
    __syncthreads();
    if (nw == 1) {
        int r = 16 * mw + g;
        float inv0 = 1.f / (LS[r * 2] + LS[r * 2 + 1]);
        float inv1 = 1.f / (LS[(r + 8) * 2] + LS[(r + 8) * 2 + 1]);
        #pragma unroll
        for (int nb = 0; nb < 8; nb++) {
            int c = 8 * nb + 2 * t4;
            float2 p0 = *(float2*)(OB + r * OBS + c);
            float2 p1 = *(float2*)(OB + (r + 8) * OBS + c);
            *(float2*)(ob + (size_t)(l0 + r) * RS + c) =
                make_float2((O[nb][0] + p0.x) * inv0, (O[nb][1] + p0.y) * inv0);
            *(float2*)(ob + (size_t)(l0 + r + 8) * RS + c) =
                make_float2((O[nb][2] + p1.x) * inv1, (O[nb][3] + p1.y) * inv1);
        }
    }
}

// ---------------- launcher ----------------
extern "C" void kernel_launch(void* const* d_in, const int* in_sizes, int n_in,
                              void* d_out, int out_size) {
    const float* q   = (const float*)d_in[0];
    const float* k   = (const float*)d_in[1];
    const float* v   = (const float*)d_in[2];
    const float* wm  = (const float*)d_in[3];
    const float* tau = (const float*)d_in[4];
    // d_in[5] = attn_mask, unused (mask_flag=False)

    cudaFuncSetAttribute(flash_kernel, cudaFuncAttributeMaxDynamicSharedMemorySize, SMEM_BYTES);

    wprep_kernel<<<L_SZ, 256>>>(wm, tau);

    dim3 grid(L_SZ / BM, B_SZ * H_SZ);
    flash_kernel<<<grid, THREADS, SMEM_BYTES>>>(q, k, v, (float*)d_out);
}

// round 10
// speedup vs baseline: 2.0685x; 1.1447x over previous
#include <cuda_runtime.h>
#include <cuda_fp16.h>
#include <cstdint>
#include <math.h>

// ---------------- problem constants ----------------
#define B_SZ 16
#define H_SZ 8
#define L_SZ 1024
#define E_SZ 64
#define RS   512                 // floats between consecutive rows (H*E)

#define BM 128
#define BN 64
#define NT 16
#define THREADS 256

// ---------------- smem byte map (fp16 tiles, 128B swizzled rows) ------------
#define QO   0                       // 128 x 64 fp16 = 16 KB
#define KO(b) (16384 + (b) * 8192)   // 64 x 64 fp16, double buffered
#define VO(b) (32768 + (b) * 8192)
#define SMEM_BYTES 49152

// precomputed tensors
__device__ __half g_kh[B_SZ * H_SZ * L_SZ * E_SZ];   // [bh][s][e] fp16
__device__ __half g_vh[B_SZ * H_SZ * L_SZ * E_SZ];
// g_w[l][s] = softmax_s(wm[l][s]/softplus(tau[l])) * (1/8) * log2(e)
__device__ float g_w[L_SZ * L_SZ];

// ---------------- helpers ----------------
__device__ __forceinline__ uint32_t smem_u32(const void* p) {
    uint32_t a;
    asm("{ .reg .u64 t; cvta.to.shared.u64 t, %1; cvt.u32.u64 %0, t; }" : "=r"(a) : "l"(p));
    return a;
}
// 128B-row XOR swizzle
__device__ __forceinline__ uint32_t swz(int r, int cb) {
    return (uint32_t)(r * 128 + (cb ^ ((r & 7) << 4)));
}
__device__ __forceinline__ float ex2f(float x) {
    float y; asm("ex2.approx.f32 %0, %1;" : "=f"(y) : "f"(x)); return y;
}

#define LDSM4(d0,d1,d2,d3,a) \
    asm volatile("ldmatrix.sync.aligned.m8n8.x4.shared.b16 {%0,%1,%2,%3}, [%4];" \
        : "=r"(d0),"=r"(d1),"=r"(d2),"=r"(d3) : "r"(a))
#define LDSM4T(d0,d1,d2,d3,a) \
    asm volatile("ldmatrix.sync.aligned.m8n8.x4.trans.shared.b16 {%0,%1,%2,%3}, [%4];" \
        : "=r"(d0),"=r"(d1),"=r"(d2),"=r"(d3) : "r"(a))
#define MMA16816(c, a0,a1,a2,a3, b0,b1) \
    asm volatile("mma.sync.aligned.m16n8k16.row.col.f32.f16.f16.f32 " \
        "{%0,%1,%2,%3},{%4,%5,%6,%7},{%8,%9},{%0,%1,%2,%3};" \
        : "+f"((c)[0]),"+f"((c)[1]),"+f"((c)[2]),"+f"((c)[3]) \
        : "r"(a0),"r"(a1),"r"(a2),"r"(a3),"r"(b0),"r"(b1))
#define CPA16(dst, src) \
    asm volatile("cp.async.cg.shared.global [%0], [%1], 16;" :: "r"(dst), "l"(src))
#define CPA_COMMIT() asm volatile("cp.async.commit_group;" ::: "memory")
#define CPA_WAIT0()  asm volatile("cp.async.wait_group 0;" ::: "memory")

__device__ __forceinline__ uint2 pack4h(float4 x) {
    half2 h0 = __floats2half2_rn(x.x, x.y);
    half2 h1 = __floats2half2_rn(x.z, x.w);
    return make_uint2(*(uint32_t*)&h0, *(uint32_t*)&h1);
}
__device__ __forceinline__ uint32_t pack2h(float a, float b) {
    half2 h = __floats2half2_rn(a, b);
    return *(uint32_t*)&h;
}

// ---------------- kernel 0: K/V fp32 -> fp16, bh-major ----------------
__global__ void kvprep_kernel(const float* __restrict__ k, const float* __restrict__ v) {
    int o = blockIdx.x * 256 + threadIdx.x;      // half4 index, 2^21 total
    int e4 = o & 15;
    int s  = (o >> 4) & 1023;
    int bh = o >> 14;
    int b = bh >> 3, h = bh & 7;
    size_t in = (((size_t)b * L_SZ + s) * H_SZ + h) * 16 + e4;   // float4 units
    ((uint2*)g_kh)[o] = pack4h(((const float4*)k)[in]);
    ((uint2*)g_vh)[o] = pack4h(((const float4*)v)[in]);
}

// ---------------- kernel 1: modulation weights ----------------
__global__ void wprep_kernel(const float* __restrict__ wm, const float* __restrict__ tau) {
    __shared__ float red_m[8];
    __shared__ float red_s[8];
    const int row = blockIdx.x, tid = threadIdx.x;
    const int warp = tid >> 5, lane = tid & 31;

    float t = tau[row];
    float sp = (t > 20.f) ? t : log1pf(__expf(t));
    float inv = 1.f / sp;

    float4 x = reinterpret_cast<const float4*>(wm + (size_t)row * L_SZ)[tid];
    x.x *= inv; x.y *= inv; x.z *= inv; x.w *= inv;

    float mx = fmaxf(fmaxf(x.x, x.y), fmaxf(x.z, x.w));
    #pragma unroll
    for (int o = 16; o; o >>= 1) mx = fmaxf(mx, __shfl_xor_sync(0xffffffffu, mx, o));
    if (lane == 0) red_m[warp] = mx;
    __syncthreads();
    float M = red_m[0];
    #pragma unroll
    for (int i = 1; i < 8; i++) M = fmaxf(M, red_m[i]);

    float e0 = __expf(x.x - M), e1 = __expf(x.y - M);
    float e2 = __expf(x.z - M), e3 = __expf(x.w - M);
    float s = e0 + e1 + e2 + e3;
    #pragma unroll
    for (int o = 16; o; o >>= 1) s += __shfl_xor_sync(0xffffffffu, s, o);
    if (lane == 0) red_s[warp] = s;
    __syncthreads();
    float S = 0.f;
    #pragma unroll
    for (int i = 0; i < 8; i++) S += red_s[i];

    float f = 0.125f / S * 1.44269504089f;   // fold 1/sqrt(E) and log2(e)
    reinterpret_cast<float4*>(g_w + (size_t)row * L_SZ)[tid] =
        make_float4(e0 * f, e1 * f, e2 * f, e3 * f);
}

// ---- kernel 2: fp16 mma flash attention, cp.async tiles, 2 CTAs/SM --------
__global__ void __launch_bounds__(THREADS, 2)
flash_kernel(const float* __restrict__ q, float* __restrict__ out) {
    extern __shared__ char smem[];
    const uint32_t sb = smem_u32(smem);

    const int tid = threadIdx.x;
    const int warp = tid >> 5, lane = tid & 31;    // 8 M-warps, 16 rows each
    const int g = lane >> 2, t4 = lane & 3;
    const int l0 = blockIdx.x * BM;
    const int bh = blockIdx.y;

    const size_t base = (size_t)(bh >> 3) * (L_SZ * RS) + (size_t)(bh & 7) * E_SZ;
    const float* qb = q + base;
    float* ob = out + base;
    const __half* khb = g_kh + (size_t)bh * (L_SZ * E_SZ);
    const __half* vhb = g_vh + (size_t)bh * (L_SZ * E_SZ);

    // chunk assignment for cp.async tile fills: 512 chunks / 256 thr = 2 each
    const int c0r = tid >> 3, c0c = (tid & 7) << 4;      // chunk 0: rows 0..31
    // chunk 1: rows 32..63 (c0r + 32)

    // ---- issue K0/V0 cp.async, then stage Q ----
    {
        CPA16(sb + KO(0) + swz(c0r, c0c), khb + c0r * 64 + (c0c >> 1));
        CPA16(sb + KO(0) + swz(c0r + 32, c0c), khb + (c0r + 32) * 64 + (c0c >> 1));
        CPA16(sb + VO(0) + swz(c0r, c0c), vhb + c0r * 64 + (c0c >> 1));
        CPA16(sb + VO(0) + swz(c0r + 32, c0c), vhb + (c0r + 32) * 64 + (c0c >> 1));
        CPA_COMMIT();
    }
    #pragma unroll
    for (int i = 0; i < 8; i++) {
        int e4 = i * THREADS + tid;              // 2048 float4
        int r = e4 >> 4, c = (e4 & 15) << 2;
        float4 x = *(const float4*)(qb + (size_t)(l0 + r) * RS + c);
        *(uint2*)(smem + QO + swz(r, c * 2)) = pack4h(x);
    }
    CPA_WAIT0();
    __syncthreads();

    // ---- persistent Q fragments (rows 16*warp..+15, k=0..63): 16 regs ----
    uint32_t QA[4][4];
    #pragma unroll
    for (int kbk = 0; kbk < 4; kbk++)
        LDSM4(QA[kbk][0], QA[kbk][1], QA[kbk][2], QA[kbk][3],
              sb + QO + swz(16 * warp + (lane & 15), kbk * 32 + ((lane >> 4) << 4)));

    float O[8][4];
    #pragma unroll
    for (int nb = 0; nb < 8; nb++) {
        O[nb][0] = 0.f; O[nb][1] = 0.f; O[nb][2] = 0.f; O[nb][3] = 0.f;
    }
    float ls0 = 0.f, ls1 = 0.f;

    for (int st = 0; st < NT; st++) {
        const int buf = st & 1;

        // issue cp.async for next tile into buf^1
        if (st < NT - 1) {
            const int s0n = (st + 1) * BN;
            CPA16(sb + KO(buf ^ 1) + swz(c0r, c0c), khb + (s0n + c0r) * 64 + (c0c >> 1));
            CPA16(sb + KO(buf ^ 1) + swz(c0r + 32, c0c), khb + (s0n + c0r + 32) * 64 + (c0c >> 1));
            CPA16(sb + VO(buf ^ 1) + swz(c0r, c0c), vhb + (s0n + c0r) * 64 + (c0c >> 1));
            CPA16(sb + VO(buf ^ 1) + swz(c0r + 32, c0c), vhb + (s0n + c0r + 32) * 64 + (c0c >> 1));
            CPA_COMMIT();
        }

        // ---- S = Q K^T : 16 LDSM4 + 32 MMA (16 rows x 64 s-cols) ----
        float S[8][4];
        #pragma unroll
        for (int nb = 0; nb < 8; nb++) {
            S[nb][0] = 0.f; S[nb][1] = 0.f; S[nb][2] = 0.f; S[nb][3] = 0.f;
        }
        #pragma unroll
        for (int s16 = 0; s16 < 4; s16++) {
            #pragma unroll
            for (int kbk = 0; kbk < 4; kbk++) {
                uint32_t Kf0, Kf1, Kf2, Kf3;
                int rk = s16 * 16 + (lane & 7) + ((lane & 16) >> 1);
                int cbk = kbk * 32 + (((lane >> 3) & 1) << 4);
                LDSM4(Kf0, Kf1, Kf2, Kf3, sb + KO(buf) + swz(rk, cbk));
                MMA16816(S[2 * s16],     QA[kbk][0], QA[kbk][1], QA[kbk][2], QA[kbk][3], Kf0, Kf1);
                MMA16816(S[2 * s16 + 1], QA[kbk][0], QA[kbk][1], QA[kbk][2], QA[kbk][3], Kf2, Kf3);
            }
        }

        // ---- softmax: p = exp2(s*w') (w' has log2e; |z|<<1 -> no max) ----
        uint32_t P[4][4];
        {
            const float* wr = g_w + (size_t)(l0 + 16 * warp + g) * L_SZ + st * BN + 2 * t4;
            #pragma unroll
            for (int nb = 0; nb < 8; nb++) {
                float2 wa = *(const float2*)(wr + nb * 8);
                float2 wb = *(const float2*)(wr + nb * 8 + 8 * L_SZ);
                float e0 = ex2f(S[nb][0] * wa.x);
                float e1 = ex2f(S[nb][1] * wa.y);
                float e2 = ex2f(S[nb][2] * wb.x);
                float e3 = ex2f(S[nb][3] * wb.y);
                ls0 += e0 + e1;
                ls1 += e2 + e3;
                P[nb >> 1][(nb & 1) * 2]     = pack2h(e0, e1);
                P[nb >> 1][(nb & 1) * 2 + 1] = pack2h(e2, e3);
            }
        }

        // ---- O += P V : 16 LDSM4T + 32 MMA (full k=64) ----
        #pragma unroll
        for (int kb = 0; kb < 4; kb++) {
            uint32_t Vf[4][4];
            #pragma unroll
            for (int n16 = 0; n16 < 4; n16++) {
                int rv = kb * 16 + (lane & 15);
                int cbv = n16 * 32 + ((lane >> 4) << 4);
                LDSM4T(Vf[n16][0], Vf[n16][1], Vf[n16][2], Vf[n16][3],
                       sb + VO(buf) + swz(rv, cbv));
            }
            #pragma unroll
            for (int nb = 0; nb < 8; nb++)
                MMA16816(O[nb], P[kb][0], P[kb][1], P[kb][2], P[kb][3],
                         Vf[nb >> 1][(nb & 1) * 2], Vf[nb >> 1][(nb & 1) * 2 + 1]);
        }

        // wait for next tile's cp.async; release buf for overwrite next iter
        if (st < NT - 1) {
            CPA_WAIT0();
            __syncthreads();
        }
    }

    // ---- epilogue: quad-reduce ls, scale, store directly ----
    ls0 += __shfl_xor_sync(0xffffffffu, ls0, 1);
    ls0 += __shfl_xor_sync(0xffffffffu, ls0, 2);
    ls1 += __shfl_xor_sync(0xffffffffu, ls1, 1);
    ls1 += __shfl_xor_sync(0xffffffffu, ls1, 2);
    float inv0 = 1.f / ls0;
    float inv1 = 1.f / ls1;

    int r = l0 + 16 * warp + g;
    #pragma unroll
    for (int nb = 0; nb < 8; nb++) {
        int c = 8 * nb + 2 * t4;
        *(float2*)(ob + (size_t)r * RS + c) =
            make_float2(O[nb][0] * inv0, O[nb][1] * inv0);
        *(float2*)(ob + (size_t)(r + 8) * RS + c) =
            make_float2(O[nb][2] * inv1, O[nb][3] * inv1);
    }
}

// ---------------- launcher ----------------
extern "C" void kernel_launch(void* const* d_in, const int* in_sizes, int n_in,
                              void* d_out, int out_size) {
    const float* q   = (const float*)d_in[0];
    const float* k   = (const float*)d_in[1];
    const float* v   = (const float*)d_in[2];
    const float* wm  = (const float*)d_in[3];
    const float* tau = (const float*)d_in[4];
    // d_in[5] = attn_mask, unused (mask_flag=False)

    cudaFuncSetAttribute(flash_kernel, cudaFuncAttributeMaxDynamicSharedMemorySize, SMEM_BYTES);

    kvprep_kernel<<<(B_SZ * H_SZ * L_SZ * E_SZ / 4) / 256, 256>>>(k, v);
    wprep_kernel<<<L_SZ, 256>>>(wm, tau);

    dim3 grid(L_SZ / BM, B_SZ * H_SZ);
    flash_kernel<<<grid, THREADS, SMEM_BYTES>>>(q, (float*)d_out);
}

// round 11
// speedup vs baseline: 2.2841x; 1.1042x over previous
#include <cuda_runtime.h>
#include <cuda_fp16.h>
#include <cstdint>
#include <math.h>

// ---------------- problem constants ----------------
#define B_SZ 16
#define H_SZ 8
#define L_SZ 1024
#define E_SZ 64
#define RS   512                 // floats between consecutive rows (H*E)

#define BM 128
#define BN 64
#define NT 16
#define THREADS 256

// ---------------- smem byte map (fp16 tiles, 128B swizzled rows) ------------
#define QO   0                       // 128 x 64 fp16 = 16 KB
#define KO(b) (16384 + (b) * 8192)   // 64 x 64 fp16, 3-stage ring
#define VO(b) (40960 + (b) * 8192)
#define SMEM_BYTES 65536

// precomputed tensors
__device__ __half g_kh[B_SZ * H_SZ * L_SZ * E_SZ];   // [bh][s][e] fp16
__device__ __half g_vh[B_SZ * H_SZ * L_SZ * E_SZ];
// g_wh[l][s] = fp16( softmax_s(wm[l][s]/softplus(tau[l])) * (1/8) * log2(e) )
__device__ __half g_wh[L_SZ * L_SZ];

// ---------------- helpers ----------------
__device__ __forceinline__ uint32_t smem_u32(const void* p) {
    uint32_t a;
    asm("{ .reg .u64 t; cvta.to.shared.u64 t, %1; cvt.u32.u64 %0, t; }" : "=r"(a) : "l"(p));
    return a;
}
// 128B-row XOR swizzle
__device__ __forceinline__ uint32_t swz(int r, int cb) {
    return (uint32_t)(r * 128 + (cb ^ ((r & 7) << 4)));
}
__device__ __forceinline__ float ex2f(float x) {
    float y; asm("ex2.approx.f32 %0, %1;" : "=f"(y) : "f"(x)); return y;
}

#define LDSM4(d0,d1,d2,d3,a) \
    asm volatile("ldmatrix.sync.aligned.m8n8.x4.shared.b16 {%0,%1,%2,%3}, [%4];" \
        : "=r"(d0),"=r"(d1),"=r"(d2),"=r"(d3) : "r"(a))
#define LDSM4T(d0,d1,d2,d3,a) \
    asm volatile("ldmatrix.sync.aligned.m8n8.x4.trans.shared.b16 {%0,%1,%2,%3}, [%4];" \
        : "=r"(d0),"=r"(d1),"=r"(d2),"=r"(d3) : "r"(a))
#define MMA16816(c, a0,a1,a2,a3, b0,b1) \
    asm volatile("mma.sync.aligned.m16n8k16.row.col.f32.f16.f16.f32 " \
        "{%0,%1,%2,%3},{%4,%5,%6,%7},{%8,%9},{%0,%1,%2,%3};" \
        : "+f"((c)[0]),"+f"((c)[1]),"+f"((c)[2]),"+f"((c)[3]) \
        : "r"(a0),"r"(a1),"r"(a2),"r"(a3),"r"(b0),"r"(b1))
#define CPA16(dst, src) \
    asm volatile("cp.async.cg.shared.global [%0], [%1], 16;" :: "r"(dst), "l"(src))
#define CPA_COMMIT() asm volatile("cp.async.commit_group;" ::: "memory")
#define CPA_WAIT0()  asm volatile("cp.async.wait_group 0;" ::: "memory")
#define CPA_WAIT1()  asm volatile("cp.async.wait_group 1;" ::: "memory")

__device__ __forceinline__ uint2 pack4h(float4 x) {
    half2 h0 = __floats2half2_rn(x.x, x.y);
    half2 h1 = __floats2half2_rn(x.z, x.w);
    return make_uint2(*(uint32_t*)&h0, *(uint32_t*)&h1);
}
__device__ __forceinline__ uint32_t pack2h(float a, float b) {
    half2 h = __floats2half2_rn(a, b);
    return *(uint32_t*)&h;
}

// ---------------- kernel 0: K/V fp32 -> fp16, bh-major ----------------
__global__ void kvprep_kernel(const float* __restrict__ k, const float* __restrict__ v) {
    int o = blockIdx.x * 256 + threadIdx.x;      // half4 index, 2^21 total
    int e4 = o & 15;
    int s  = (o >> 4) & 1023;
    int bh = o >> 14;
    int b = bh >> 3, h = bh & 7;
    size_t in = (((size_t)b * L_SZ + s) * H_SZ + h) * 16 + e4;   // float4 units
    ((uint2*)g_kh)[o] = pack4h(((const float4*)k)[in]);
    ((uint2*)g_vh)[o] = pack4h(((const float4*)v)[in]);
}

// ---------------- kernel 1: modulation weights (fp16 out) ----------------
__global__ void wprep_kernel(const float* __restrict__ wm, const float* __restrict__ tau) {
    __shared__ float red_m[8];
    __shared__ float red_s[8];
    const int row = blockIdx.x, tid = threadIdx.x;
    const int warp = tid >> 5, lane = tid & 31;

    float t = tau[row];
    float sp = (t > 20.f) ? t : log1pf(__expf(t));
    float inv = 1.f / sp;

    float4 x = reinterpret_cast<const float4*>(wm + (size_t)row * L_SZ)[tid];
    x.x *= inv; x.y *= inv; x.z *= inv; x.w *= inv;

    float mx = fmaxf(fmaxf(x.x, x.y), fmaxf(x.z, x.w));
    #pragma unroll
    for (int o = 16; o; o >>= 1) mx = fmaxf(mx, __shfl_xor_sync(0xffffffffu, mx, o));
    if (lane == 0) red_m[warp] = mx;
    __syncthreads();
    float M = red_m[0];
    #pragma unroll
    for (int i = 1; i < 8; i++) M = fmaxf(M, red_m[i]);

    float e0 = __expf(x.x - M), e1 = __expf(x.y - M);
    float e2 = __expf(x.z - M), e3 = __expf(x.w - M);
    float s = e0 + e1 + e2 + e3;
    #pragma unroll
    for (int o = 16; o; o >>= 1) s += __shfl_xor_sync(0xffffffffu, s, o);
    if (lane == 0) red_s[warp] = s;
    __syncthreads();
    float S = 0.f;
    #pragma unroll
    for (int i = 0; i < 8; i++) S += red_s[i];

    float f = 0.125f / S * 1.44269504089f;   // fold 1/sqrt(E) and log2(e)
    ((uint2*)g_wh)[row * (L_SZ / 4) + tid] =
        pack4h(make_float4(e0 * f, e1 * f, e2 * f, e3 * f));
}

// -- kernel 2: fp16 mma flash attention, 3-stage cp.async, 2 CTAs/SM --------
__global__ void __launch_bounds__(THREADS, 2)
flash_kernel(const float* __restrict__ q, float* __restrict__ out) {
    extern __shared__ char smem[];
    const uint32_t sb = smem_u32(smem);

    const int tid = threadIdx.x;
    const int warp = tid >> 5, lane = tid & 31;    // 8 M-warps, 16 rows each
    const int g = lane >> 2, t4 = lane & 3;
    const int l0 = blockIdx.x * BM;
    const int bh = blockIdx.y;

    const size_t base = (size_t)(bh >> 3) * (L_SZ * RS) + (size_t)(bh & 7) * E_SZ;
    const float* qb = q + base;
    float* ob = out + base;
    const __half* khb = g_kh + (size_t)bh * (L_SZ * E_SZ);
    const __half* vhb = g_vh + (size_t)bh * (L_SZ * E_SZ);
    const __half* whb = g_wh + (size_t)(l0 + 16 * warp + g) * L_SZ + 2 * t4;

    // chunk assignment for cp.async tile fills: 2 x 16B per thread per tile
    const int c0r = tid >> 3, c0c = (tid & 7) << 4;      // rows 0..31 / +32

    // ---- prologue: issue tiles 0 and 1, stage Q ----
    #pragma unroll
    for (int t = 0; t < 2; t++) {
        const int s0 = t * BN;
        CPA16(sb + KO(t) + swz(c0r, c0c), khb + (s0 + c0r) * 64 + (c0c >> 1));
        CPA16(sb + KO(t) + swz(c0r + 32, c0c), khb + (s0 + c0r + 32) * 64 + (c0c >> 1));
        CPA16(sb + VO(t) + swz(c0r, c0c), vhb + (s0 + c0r) * 64 + (c0c >> 1));
        CPA16(sb + VO(t) + swz(c0r + 32, c0c), vhb + (s0 + c0r + 32) * 64 + (c0c >> 1));
        CPA_COMMIT();
    }
    #pragma unroll
    for (int i = 0; i < 8; i++) {
        int e4 = i * THREADS + tid;              // 2048 float4
        int r = e4 >> 4, c = (e4 & 15) << 2;
        float4 x = *(const float4*)(qb + (size_t)(l0 + r) * RS + c);
        *(uint2*)(smem + QO + swz(r, c * 2)) = pack4h(x);
    }
    CPA_WAIT1();        // tile 0 landed
    __syncthreads();    // Q + tile 0 visible to all warps

    // ---- persistent Q fragments (rows 16*warp..+15, k=0..63): 16 regs ----
    uint32_t QA[4][4];
    #pragma unroll
    for (int kbk = 0; kbk < 4; kbk++)
        LDSM4(QA[kbk][0], QA[kbk][1], QA[kbk][2], QA[kbk][3],
              sb + QO + swz(16 * warp + (lane & 15), kbk * 32 + ((lane >> 4) << 4)));

    float O[8][4];
    #pragma unroll
    for (int nb = 0; nb < 8; nb++) {
        O[nb][0] = 0.f; O[nb][1] = 0.f; O[nb][2] = 0.f; O[nb][3] = 0.f;
    }
    float ls0 = 0.f, ls1 = 0.f;

    for (int st = 0; st < NT; st++) {
        const int buf = st % 3;

        // issue cp.async for tile st+2 into its ring slot (read at st-1, freed)
        if (st + 2 < NT) {
            const int nb3 = (st + 2) % 3;
            const int s0n = (st + 2) * BN;
            CPA16(sb + KO(nb3) + swz(c0r, c0c), khb + (s0n + c0r) * 64 + (c0c >> 1));
            CPA16(sb + KO(nb3) + swz(c0r + 32, c0c), khb + (s0n + c0r + 32) * 64 + (c0c >> 1));
            CPA16(sb + VO(nb3) + swz(c0r, c0c), vhb + (s0n + c0r) * 64 + (c0c >> 1));
            CPA16(sb + VO(nb3) + swz(c0r + 32, c0c), vhb + (s0n + c0r + 32) * 64 + (c0c >> 1));
            CPA_COMMIT();
        }

        // prefetch w fragments (fp16, L2-resident) — hidden behind S MMAs
        uint32_t wl0[8], wl1[8];
        {
            const __half* wr = whb + st * BN;
            #pragma unroll
            for (int nb = 0; nb < 8; nb++) {
                wl0[nb] = *(const uint32_t*)(wr + nb * 8);
                wl1[nb] = *(const uint32_t*)(wr + nb * 8 + 8 * L_SZ);
            }
        }

        // ---- S = Q K^T : 16 LDSM4 + 32 MMA (16 rows x 64 s-cols) ----
        float S[8][4];
        #pragma unroll
        for (int nb = 0; nb < 8; nb++) {
            S[nb][0] = 0.f; S[nb][1] = 0.f; S[nb][2] = 0.f; S[nb][3] = 0.f;
        }
        #pragma unroll
        for (int s16 = 0; s16 < 4; s16++) {
            #pragma unroll
            for (int kbk = 0; kbk < 4; kbk++) {
                uint32_t Kf0, Kf1, Kf2, Kf3;
                int rk = s16 * 16 + (lane & 7) + ((lane & 16) >> 1);
                int cbk = kbk * 32 + (((lane >> 3) & 1) << 4);
                LDSM4(Kf0, Kf1, Kf2, Kf3, sb + KO(buf) + swz(rk, cbk));
                MMA16816(S[2 * s16],     QA[kbk][0], QA[kbk][1], QA[kbk][2], QA[kbk][3], Kf0, Kf1);
                MMA16816(S[2 * s16 + 1], QA[kbk][0], QA[kbk][1], QA[kbk][2], QA[kbk][3], Kf2, Kf3);
            }
        }

        // ---- softmax: p = exp2(s*w') (w' has log2e; |z|<<1 -> no max) ----
        uint32_t P[4][4];
        #pragma unroll
        for (int nb = 0; nb < 8; nb++) {
            float2 wa = __half22float2(*(half2*)&wl0[nb]);
            float2 wb = __half22float2(*(half2*)&wl1[nb]);
            float e0 = ex2f(S[nb][0] * wa.x);
            float e1 = ex2f(S[nb][1] * wa.y);
            float e2 = ex2f(S[nb][2] * wb.x);
            float e3 = ex2f(S[nb][3] * wb.y);
            ls0 += e0 + e1;
            ls1 += e2 + e3;
            P[nb >> 1][(nb & 1) * 2]     = pack2h(e0, e1);
            P[nb >> 1][(nb & 1) * 2 + 1] = pack2h(e2, e3);
        }

        // ---- O += P V : 16 LDSM4T + 32 MMA (full k=64) ----
        #pragma unroll
        for (int kb = 0; kb < 4; kb++) {
            uint32_t Vf[4][4];
            #pragma unroll
            for (int n16 = 0; n16 < 4; n16++) {
                int rv = kb * 16 + (lane & 15);
                int cbv = n16 * 32 + ((lane >> 4) << 4);
                LDSM4T(Vf[n16][0], Vf[n16][1], Vf[n16][2], Vf[n16][3],
                       sb + VO(buf) + swz(rv, cbv));
            }
            #pragma unroll
            for (int nb = 0; nb < 8; nb++)
                MMA16816(O[nb], P[kb][0], P[kb][1], P[kb][2], P[kb][3],
                         Vf[nb >> 1][(nb & 1) * 2], Vf[nb >> 1][(nb & 1) * 2 + 1]);
        }

        // ensure tile st+1 landed; barrier frees this iter's ring slot
        if (st < NT - 1) {
            if (st + 2 < NT) CPA_WAIT1(); else CPA_WAIT0();
            __syncthreads();
        }
    }

    // ---- epilogue: quad-reduce ls, scale, store directly ----
    ls0 += __shfl_xor_sync(0xffffffffu, ls0, 1);
    ls0 += __shfl_xor_sync(0xffffffffu, ls0, 2);
    ls1 += __shfl_xor_sync(0xffffffffu, ls1, 1);
    ls1 += __shfl_xor_sync(0xffffffffu, ls1, 2);
    float inv0 = 1.f / ls0;
    float inv1 = 1.f / ls1;

    int r = l0 + 16 * warp + g;
    #pragma unroll
    for (int nb = 0; nb < 8; nb++) {
        int c = 8 * nb + 2 * t4;
        *(float2*)(ob + (size_t)r * RS + c) =
            make_float2(O[nb][0] * inv0, O[nb][1] * inv0);
        *(float2*)(ob + (size_t)(r + 8) * RS + c) =
            make_float2(O[nb][2] * inv1, O[nb][3] * inv1);
    }
}

// ---------------- launcher ----------------
extern "C" void kernel_launch(void* const* d_in, const int* in_sizes, int n_in,
                              void* d_out, int out_size) {
    const float* q   = (const float*)d_in[0];
    const float* k   = (const float*)d_in[1];
    const float* v   = (const float*)d_in[2];
    const float* wm  = (const float*)d_in[3];
    const float* tau = (const float*)d_in[4];
    // d_in[5] = attn_mask, unused (mask_flag=False)

    cudaFuncSetAttribute(flash_kernel, cudaFuncAttributeMaxDynamicSharedMemorySize, SMEM_BYTES);

    kvprep_kernel<<<(B_SZ * H_SZ * L_SZ * E_SZ / 4) / 256, 256>>>(k, v);
    wprep_kernel<<<L_SZ, 256>>>(wm, tau);

    dim3 grid(L_SZ / BM, B_SZ * H_SZ);
    flash_kernel<<<grid, THREADS, SMEM_BYTES>>>(q, (float*)d_out);
}